// round 5
// baseline (speedup 1.0000x reference)
#include <cuda_runtime.h>
#include <cstdint>

#define N_NODES 2048
#define IN_DIM 32
#define LATENT 64
#define PADA 68    // a-table row stride (floats)
#define PADB 132   // b-table row stride (floats)

typedef unsigned long long ull;

// Scratch (__device__ globals: allocation-free rule)
__device__ float  g_zi[N_NODES * LATENT];       // [n][l]
__device__ float  g_zjbT[LATENT * N_NODES];     // [l][n] transposed
__device__ float2 g_wsd[LATENT];                // 0.495*w, duplicated
__device__ float  g_aw2[N_NODES];               // 0.505 * dot(w, zi[i])
__device__ float  g_cw2[N_NODES];               // 0.505 * dot(w, zjb[j]) + b_e2

// ---------------------------------------------------------------------------
// Kernel 1: per-node precompute, 16 nodes/block -> 128 blocks (single wave).
// ---------------------------------------------------------------------------
__global__ __launch_bounds__(256) void node_precompute_kernel(
    const float* __restrict__ x,
    const float* __restrict__ W_ne, const float* __restrict__ b_ne,
    const float* __restrict__ W_e1a, const float* __restrict__ W_e1b,
    const float* __restrict__ b_e1,
    const float* __restrict__ w_e2, const float* __restrict__ b_e2)
{
    __shared__ float sWne[IN_DIM * LATENT];
    __shared__ float sWa[LATENT * LATENT];
    __shared__ float sWb[LATENT * LATENT];
    __shared__ float sx[16][IN_DIM];
    __shared__ float sz[16][LATENT];
    __shared__ float szi[16][LATENT];
    __shared__ float szjb[16][LATENT];

    const int tid = threadIdx.x;
    const int nb = blockIdx.x * 16;

    for (int i = tid; i < IN_DIM * LATENT / 4; i += 256)
        ((float4*)sWne)[i] = ((const float4*)W_ne)[i];
    for (int i = tid; i < LATENT * LATENT / 4; i += 256) {
        ((float4*)sWa)[i] = ((const float4*)W_e1a)[i];
        ((float4*)sWb)[i] = ((const float4*)W_e1b)[i];
    }
    if (tid < 128)
        ((float4*)sx)[tid] = ((const float4*)&x[nb * IN_DIM])[tid];
    __syncthreads();

#pragma unroll
    for (int r = 0; r < 4; r++) {
        int idx = tid + 256 * r;
        int n = idx >> 6, l = idx & 63;
        float acc = b_ne[l];
#pragma unroll
        for (int k = 0; k < IN_DIM; k++)
            acc = fmaf(sx[n][k], sWne[k * LATENT + l], acc);
        sz[n][l] = fmaxf(acc, 0.01f * acc);
    }
    __syncthreads();

#pragma unroll
    for (int r = 0; r < 4; r++) {
        int idx = tid + 256 * r;
        int n = idx >> 6, l = idx & 63;
        float zi_v = 0.0f;
        float zjb_v = b_e1[l];
#pragma unroll
        for (int k = 0; k < LATENT; k++) {
            float zk = sz[n][k];
            zi_v  = fmaf(zk, sWa[k * LATENT + l], zi_v);
            zjb_v = fmaf(zk, sWb[k * LATENT + l], zjb_v);
        }
        szi[n][l] = zi_v;
        szjb[n][l] = zjb_v;
        g_zi[(nb + n) * LATENT + l] = zi_v;
        g_zjbT[l * N_NODES + nb + n] = zjb_v;
    }
    __syncthreads();

    const int wid = tid >> 5, lane = tid & 31;
    const float w1 = w_e2[lane], w2 = w_e2[lane + 32];
#pragma unroll
    for (int s = 0; s < 2; s++) {
        const int n = 2 * wid + s;
        float s1 = w1 * szi[n][lane]  + w2 * szi[n][lane + 32];
        float s2 = w1 * szjb[n][lane] + w2 * szjb[n][lane + 32];
#pragma unroll
        for (int off = 16; off > 0; off >>= 1) {
            s1 += __shfl_down_sync(0xffffffffu, s1, off);
            s2 += __shfl_down_sync(0xffffffffu, s2, off);
        }
        if (lane == 0) {
            g_aw2[nb + n] = 0.505f * s1;
            g_cw2[nb + n] = 0.505f * s2 + b_e2[0];
        }
    }
    if (blockIdx.x == 0 && tid < LATENT) {
        float w = 0.495f * w_e2[tid];
        g_wsd[tid] = make_float2(w, w);
    }
}

// ---------------------------------------------------------------------------
// Kernel 2: 64x128 tile per block, 256 threads, 4i x 8j outputs/thread,
// packed f32x2 math, a-pairs built in-register (no dup table).
// 4 blocks/SM -> all 512 blocks in one wave.
// logit(i,j) = aw2[i] + cw2[j] + sum_l ws[l] * |zi[i,l] + zjb[j,l]|
// out = (sigmoid(logit) + 1e-8) * exp(gumbel)
// ---------------------------------------------------------------------------
__global__ __launch_bounds__(256, 4) void edge_prob_kernel(
    const float* __restrict__ gumbel, float* __restrict__ out)
{
    extern __shared__ char smem_raw[];
    float*  s_a   = (float*)smem_raw;                      // [64][PADA] 17408B
    float*  s_b   = (float*)(smem_raw + 17408);            // [64][PADB] 33792B
    float2* s_wsd = (float2*)(smem_raw + 51200);           // [64] dup     512B
    float*  s_aw  = (float*)(smem_raw + 51712);            // [64]
    float*  s_cw  = (float*)(smem_raw + 51968);            // [128]

    const int tid = threadIdx.x;
    const int ibase = blockIdx.y * 64;
    const int jbase = blockIdx.x * 128;

    // load phase (coalesced float4, padded conflict-free smem rows)
#pragma unroll
    for (int t = tid; t < 1024; t += 256) {
        int r = t >> 4, c4 = (t & 15) * 4;
        *(float4*)&s_a[r * PADA + c4] =
            *(const float4*)&g_zi[(size_t)(ibase + r) * LATENT + c4];
    }
#pragma unroll
    for (int t = tid; t < 2048; t += 256) {
        int r = t >> 5, c4 = (t & 31) * 4;
        *(float4*)&s_b[r * PADB + c4] =
            *(const float4*)&g_zjbT[(size_t)r * N_NODES + jbase + c4];
    }
    if (tid < 64) {
        s_wsd[tid] = g_wsd[tid];
        s_aw[tid] = g_aw2[ibase + tid];
    }
    if (tid < 128) s_cw[tid] = g_cw2[jbase + tid];
    __syncthreads();

    const int tx = tid & 15;   // j: cols tx*4..+3 and 64+tx*4..+3
    const int ty = tid >> 4;   // i: rows ty*4..+3
    const int arow = ty * 4;

    ull acc[4][4];
#pragma unroll
    for (int ii = 0; ii < 4; ii++)
#pragma unroll
        for (int q = 0; q < 4; q++) acc[ii][q] = 0ull;

    const ull ABSM = 0x7fffffff7fffffffULL;

#pragma unroll 4
    for (int lc = 0; lc < 32; lc++) {          // 2 latents per iter
        ull w0, w1;
        {
            ulonglong2 wv = *(const ulonglong2*)&s_wsd[2 * lc];
            w0 = wv.x; w1 = wv.y;
        }
        ull b[2][4];
        {
            const float* base0 = &s_b[(2 * lc) * PADB + tx * 4];
            ulonglong2 t0 = *(const ulonglong2*)base0;
            ulonglong2 t1 = *(const ulonglong2*)(base0 + 64);
            b[0][0] = t0.x; b[0][1] = t0.y; b[0][2] = t1.x; b[0][3] = t1.y;
            const float* base1 = base0 + PADB;
            ulonglong2 t2 = *(const ulonglong2*)base1;
            ulonglong2 t3 = *(const ulonglong2*)(base1 + 64);
            b[1][0] = t2.x; b[1][1] = t2.y; b[1][2] = t3.x; b[1][3] = t3.y;
        }
#pragma unroll
        for (int ii = 0; ii < 4; ii++) {
            // two a-scalars for latents 2lc, 2lc+1 (one LDS64, warp-broadcast)
            const float2 af = *(const float2*)&s_a[(arow + ii) * PADA + 2 * lc];
            ull a0, a1;
            {
                unsigned r0 = __float_as_uint(af.x);
                unsigned r1 = __float_as_uint(af.y);
                asm("mov.b64 %0, {%1, %1};" : "=l"(a0) : "r"(r0));
                asm("mov.b64 %0, {%1, %1};" : "=l"(a1) : "r"(r1));
            }
#pragma unroll
            for (int q = 0; q < 4; q++) {
                ull v;
                asm("add.rn.f32x2 %0, %1, %2;" : "=l"(v) : "l"(a0), "l"(b[0][q]));
                v &= ABSM;
                asm("fma.rn.f32x2 %0, %1, %2, %3;"
                    : "=l"(acc[ii][q]) : "l"(w0), "l"(v), "l"(acc[ii][q]));
                asm("add.rn.f32x2 %0, %1, %2;" : "=l"(v) : "l"(a1), "l"(b[1][q]));
                v &= ABSM;
                asm("fma.rn.f32x2 %0, %1, %2, %3;"
                    : "=l"(acc[ii][q]) : "l"(w1), "l"(v), "l"(acc[ii][q]));
            }
        }
    }

    // epilogue
#pragma unroll
    for (int ii = 0; ii < 4; ii++) {
        const int il = arow + ii;
        const int i = ibase + il;
        const float base_i = s_aw[il];
#pragma unroll
        for (int g = 0; g < 2; g++) {
            const int jl = g * 64 + tx * 4;
            const size_t off = (size_t)i * N_NODES + jbase + jl;
            const float4 gv = *(const float4*)&gumbel[off];
            const float g4[4] = {gv.x, gv.y, gv.z, gv.w};

            float accf[4];
#pragma unroll
            for (int p = 0; p < 2; p++) {
                unsigned lo, hi;
                asm("mov.b64 {%0, %1}, %2;" : "=r"(lo), "=r"(hi)
                    : "l"(acc[ii][g * 2 + p]));
                accf[p * 2 + 0] = __uint_as_float(lo);
                accf[p * 2 + 1] = __uint_as_float(hi);
            }

            float4 o;
            float* op = &o.x;
#pragma unroll
            for (int jj = 0; jj < 4; jj++) {
                float logit = accf[jj] + base_i + s_cw[jl + jj];
                float e = __expf(-logit);
                float p = __fdividef(1.0f, 1.0f + e);
                op[jj] = (p + 1e-8f) * __expf(g4[jj]);
            }
            *(float4*)&out[off] = o;
        }
    }
}

// ---------------------------------------------------------------------------
// Inputs (metadata order):
// 0:x [N,32] 1:in_adj [N,N](unused) 2:gumbel [N,N] 3:W_ne [32,64] 4:b_ne [64]
// 5:W_e1a [64,64] 6:W_e1b [64,64] 7:b_e1 [64] 8:w_e2 [64] 9:b_e2 []
// out: [N,N] float32
// ---------------------------------------------------------------------------
extern "C" void kernel_launch(void* const* d_in, const int* in_sizes, int n_in,
                              void* d_out, int out_size)
{
    const float* x      = (const float*)d_in[0];
    const float* gumbel = (const float*)d_in[2];
    const float* W_ne   = (const float*)d_in[3];
    const float* b_ne   = (const float*)d_in[4];
    const float* W_e1a  = (const float*)d_in[5];
    const float* W_e1b  = (const float*)d_in[6];
    const float* b_e1   = (const float*)d_in[7];
    const float* w_e2   = (const float*)d_in[8];
    const float* b_e2   = (const float*)d_in[9];
    float* out = (float*)d_out;

    node_precompute_kernel<<<N_NODES / 16, 256>>>(x, W_ne, b_ne, W_e1a, W_e1b,
                                                  b_e1, w_e2, b_e2);

    static bool attr_set = false;
    if (!attr_set) {
        cudaFuncSetAttribute(edge_prob_kernel,
                             cudaFuncAttributeMaxDynamicSharedMemorySize, 52480);
        attr_set = true;
    }
    dim3 grid(N_NODES / 128, N_NODES / 64);
    edge_prob_kernel<<<grid, 256, 52480>>>(gumbel, out);
}

// round 7
// speedup vs baseline: 1.1387x; 1.1387x over previous
#include <cuda_runtime.h>
#include <cstdint>

#define N_NODES 2048
#define IN_DIM 32
#define LATENT 64
#define PADA 68    // a-table row stride (floats); 272B = 16B-aligned rows

typedef unsigned long long ull;

// Scratch (__device__ globals: allocation-free rule)
__device__ float  g_zi[N_NODES * LATENT];       // [n][l]
__device__ float  g_zjbT[LATENT * N_NODES];     // [l][n] transposed
__device__ float2 g_wsd[LATENT];                // 0.495*w, duplicated
__device__ float  g_aw2[N_NODES];               // 0.505 * dot(w, zi[i])
__device__ float  g_cw2[N_NODES];               // 0.505 * dot(w, zjb[j]) + b_e2

// ---------------------------------------------------------------------------
// Kernel 1: per-node precompute, 16 nodes/block -> 128 blocks (single wave).
// ---------------------------------------------------------------------------
__global__ __launch_bounds__(256) void node_precompute_kernel(
    const float* __restrict__ x,
    const float* __restrict__ W_ne, const float* __restrict__ b_ne,
    const float* __restrict__ W_e1a, const float* __restrict__ W_e1b,
    const float* __restrict__ b_e1,
    const float* __restrict__ w_e2, const float* __restrict__ b_e2)
{
    __shared__ float sWne[IN_DIM * LATENT];
    __shared__ float sWa[LATENT * LATENT];
    __shared__ float sWb[LATENT * LATENT];
    __shared__ float sx[16][IN_DIM];
    __shared__ float sz[16][LATENT];
    __shared__ float szi[16][LATENT];
    __shared__ float szjb[16][LATENT];

    const int tid = threadIdx.x;
    const int nb = blockIdx.x * 16;

    for (int i = tid; i < IN_DIM * LATENT / 4; i += 256)
        ((float4*)sWne)[i] = ((const float4*)W_ne)[i];
    for (int i = tid; i < LATENT * LATENT / 4; i += 256) {
        ((float4*)sWa)[i] = ((const float4*)W_e1a)[i];
        ((float4*)sWb)[i] = ((const float4*)W_e1b)[i];
    }
    if (tid < 128)
        ((float4*)sx)[tid] = ((const float4*)&x[nb * IN_DIM])[tid];
    __syncthreads();

#pragma unroll
    for (int r = 0; r < 4; r++) {
        int idx = tid + 256 * r;
        int n = idx >> 6, l = idx & 63;
        float acc = b_ne[l];
#pragma unroll
        for (int k = 0; k < IN_DIM; k++)
            acc = fmaf(sx[n][k], sWne[k * LATENT + l], acc);
        sz[n][l] = fmaxf(acc, 0.01f * acc);
    }
    __syncthreads();

#pragma unroll
    for (int r = 0; r < 4; r++) {
        int idx = tid + 256 * r;
        int n = idx >> 6, l = idx & 63;
        float zi_v = 0.0f;
        float zjb_v = b_e1[l];
#pragma unroll
        for (int k = 0; k < LATENT; k++) {
            float zk = sz[n][k];
            zi_v  = fmaf(zk, sWa[k * LATENT + l], zi_v);
            zjb_v = fmaf(zk, sWb[k * LATENT + l], zjb_v);
        }
        szi[n][l] = zi_v;
        szjb[n][l] = zjb_v;
        g_zi[(nb + n) * LATENT + l] = zi_v;
        g_zjbT[l * N_NODES + nb + n] = zjb_v;
    }
    __syncthreads();

    const int wid = tid >> 5, lane = tid & 31;
    const float w1 = w_e2[lane], w2 = w_e2[lane + 32];
#pragma unroll
    for (int s = 0; s < 2; s++) {
        const int n = 2 * wid + s;
        float s1 = w1 * szi[n][lane]  + w2 * szi[n][lane + 32];
        float s2 = w1 * szjb[n][lane] + w2 * szjb[n][lane + 32];
#pragma unroll
        for (int off = 16; off > 0; off >>= 1) {
            s1 += __shfl_down_sync(0xffffffffu, s1, off);
            s2 += __shfl_down_sync(0xffffffffu, s2, off);
        }
        if (lane == 0) {
            g_aw2[nb + n] = 0.505f * s1;
            g_cw2[nb + n] = 0.505f * s2 + b_e2[0];
        }
    }
    if (blockIdx.x == 0 && tid < LATENT) {
        float w = 0.495f * w_e2[tid];
        g_wsd[tid] = make_float2(w, w);
    }
}

// ---------------------------------------------------------------------------
// Kernel 2: 64x64 tile per block, 256 threads, 4i x 4j outputs/thread,
// packed f32x2 math. 5 blocks/SM, grid 1024 (dynamic load balance).
// logit(i,j) = aw2[i] + cw2[j] + sum_l ws[l] * |zi[i,l] + zjb[j,l]|
// out = (sigmoid(logit) + 1e-8) * exp(gumbel)
// ---------------------------------------------------------------------------
__global__ __launch_bounds__(256, 5) void edge_prob_kernel(
    const float* __restrict__ gumbel, float* __restrict__ out)
{
    extern __shared__ char smem_raw[];
    float*  s_a   = (float*)smem_raw;                      // [64][PADA] 17408B
    float*  s_b   = (float*)(smem_raw + 17408);            // [64][64]   16384B
    float2* s_wsd = (float2*)(smem_raw + 33792);           // [64] dup     512B
    float*  s_aw  = (float*)(smem_raw + 34304);            // [64]
    float*  s_cw  = (float*)(smem_raw + 34560);            // [64]

    const int tid = threadIdx.x;
    const int ibase = blockIdx.y * 64;
    const int jbase = blockIdx.x * 64;

    // load phase (coalesced float4, 16B-aligned smem rows)
#pragma unroll
    for (int t = tid; t < 1024; t += 256) {
        int r = t >> 4, c4 = (t & 15) * 4;
        *(float4*)&s_a[r * PADA + c4] =
            *(const float4*)&g_zi[(size_t)(ibase + r) * LATENT + c4];
    }
#pragma unroll
    for (int t = tid; t < 1024; t += 256) {
        int r = t >> 4, c4 = (t & 15) * 4;
        *(float4*)&s_b[r * 64 + c4] =
            *(const float4*)&g_zjbT[(size_t)r * N_NODES + jbase + c4];
    }
    if (tid < 64) {
        s_wsd[tid] = g_wsd[tid];
        s_aw[tid] = g_aw2[ibase + tid];
        s_cw[tid] = g_cw2[jbase + tid];
    }
    __syncthreads();

    const int tx = tid & 15;   // j: cols tx*4..+3
    const int ty = tid >> 4;   // i: rows ty*4..+3
    const int arow = ty * 4;

    ull acc[4][2];
#pragma unroll
    for (int ii = 0; ii < 4; ii++) { acc[ii][0] = 0ull; acc[ii][1] = 0ull; }

    const ull ABSM = 0x7fffffff7fffffffULL;

#pragma unroll 4
    for (int lc = 0; lc < 32; lc++) {          // 2 latents per iter
        ull w0, w1;
        {
            ulonglong2 wv = *(const ulonglong2*)&s_wsd[2 * lc];
            w0 = wv.x; w1 = wv.y;
        }
        ull b0[2], b1[2];
        {
            ulonglong2 t0 = *(const ulonglong2*)&s_b[(2 * lc) * 64 + tx * 4];
            b0[0] = t0.x; b0[1] = t0.y;
            ulonglong2 t1 = *(const ulonglong2*)&s_b[(2 * lc + 1) * 64 + tx * 4];
            b1[0] = t1.x; b1[1] = t1.y;
        }
#pragma unroll
        for (int ii = 0; ii < 4; ii++) {
            const float2 af = *(const float2*)&s_a[(arow + ii) * PADA + 2 * lc];
            ull a0, a1;
            {
                unsigned r0 = __float_as_uint(af.x);
                unsigned r1 = __float_as_uint(af.y);
                asm("mov.b64 %0, {%1, %1};" : "=l"(a0) : "r"(r0));
                asm("mov.b64 %0, {%1, %1};" : "=l"(a1) : "r"(r1));
            }
#pragma unroll
            for (int q = 0; q < 2; q++) {
                ull v;
                asm("add.rn.f32x2 %0, %1, %2;" : "=l"(v) : "l"(a0), "l"(b0[q]));
                v &= ABSM;
                asm("fma.rn.f32x2 %0, %1, %2, %3;"
                    : "=l"(acc[ii][q]) : "l"(w0), "l"(v), "l"(acc[ii][q]));
                asm("add.rn.f32x2 %0, %1, %2;" : "=l"(v) : "l"(a1), "l"(b1[q]));
                v &= ABSM;
                asm("fma.rn.f32x2 %0, %1, %2, %3;"
                    : "=l"(acc[ii][q]) : "l"(w1), "l"(v), "l"(acc[ii][q]));
            }
        }
    }

    // epilogue
#pragma unroll
    for (int ii = 0; ii < 4; ii++) {
        const int il = arow + ii;
        const int i = ibase + il;
        const float base_i = s_aw[il];
        const int jl = tx * 4;
        const size_t off = (size_t)i * N_NODES + jbase + jl;
        const float4 gv = *(const float4*)&gumbel[off];
        const float g4[4] = {gv.x, gv.y, gv.z, gv.w};

        float accf[4];
#pragma unroll
        for (int p = 0; p < 2; p++) {
            unsigned lo, hi;
            asm("mov.b64 {%0, %1}, %2;" : "=r"(lo), "=r"(hi) : "l"(acc[ii][p]));
            accf[p * 2 + 0] = __uint_as_float(lo);
            accf[p * 2 + 1] = __uint_as_float(hi);
        }

        float4 o;
        float* op = &o.x;
#pragma unroll
        for (int jj = 0; jj < 4; jj++) {
            float logit = accf[jj] + base_i + s_cw[jl + jj];
            float e = __expf(-logit);
            float p = __fdividef(1.0f, 1.0f + e);
            op[jj] = (p + 1e-8f) * __expf(g4[jj]);
        }
        *(float4*)&out[off] = o;
    }
}

// ---------------------------------------------------------------------------
// Inputs (metadata order):
// 0:x [N,32] 1:in_adj [N,N](unused) 2:gumbel [N,N] 3:W_ne [32,64] 4:b_ne [64]
// 5:W_e1a [64,64] 6:W_e1b [64,64] 7:b_e1 [64] 8:w_e2 [64] 9:b_e2 []
// out: [N,N] float32
// ---------------------------------------------------------------------------
extern "C" void kernel_launch(void* const* d_in, const int* in_sizes, int n_in,
                              void* d_out, int out_size)
{
    const float* x      = (const float*)d_in[0];
    const float* gumbel = (const float*)d_in[2];
    const float* W_ne   = (const float*)d_in[3];
    const float* b_ne   = (const float*)d_in[4];
    const float* W_e1a  = (const float*)d_in[5];
    const float* W_e1b  = (const float*)d_in[6];
    const float* b_e1   = (const float*)d_in[7];
    const float* w_e2   = (const float*)d_in[8];
    const float* b_e2   = (const float*)d_in[9];
    float* out = (float*)d_out;

    node_precompute_kernel<<<N_NODES / 16, 256>>>(x, W_ne, b_ne, W_e1a, W_e1b,
                                                  b_e1, w_e2, b_e2);

    static bool attr_set = false;
    if (!attr_set) {
        cudaFuncSetAttribute(edge_prob_kernel,
                             cudaFuncAttributeMaxDynamicSharedMemorySize, 34816);
        attr_set = true;
    }
    dim3 grid(N_NODES / 64, N_NODES / 64);
    edge_prob_kernel<<<grid, 256, 34816>>>(gumbel, out);
}